// round 8
// baseline (speedup 1.0000x reference)
#include <cuda_runtime.h>
#include <cuda_bf16.h>
#include <cstdint>

// ---------------------------------------------------------------------------
// TimeAwareKAN via single GEMM  out[m,o] = sum_k F[m,k] * W[o,k] + b[o]
//   M = 49152, K = 768 (6 families x 128), O = 512
//   family j==0: silu(x_in); j=1..5: exp(-(2*(x_in - g_{j-1}))^2)
// compute_103 toolchain => no tcgen05. Warp-level HMMA m16n8k16 bf16,
// hi/lo 3-product split (~1e-5), cp.async double-buffered W stream,
// ldmatrix from SW128-swizzled smem.
// R7: 512 threads / 16 warps (occ 12.5%->25%), warp tile 32x32, regs <=128.
// t_indices is int32 on device (JAX x64 disabled).
// ---------------------------------------------------------------------------

#define B_   4
#define H_   24
#define N_   512
#define C_   120
#define D_   128
#define O_   512
#define G_   5
#define M_TOTAL (B_ * H_ * N_)
#define K_TOTAL 768

#define BM 128
#define BN 128
#define KC 64                    // 64 bf16 = 128B rows -> SW128 native
#define NCHUNK (K_TOTAL / KC)    // 12
#define THREADS 512

// SMEM: F bufs 2 x (hi 16KB + lo 16KB) at 0; W bufs 2 x (hi 16KB + lo 16KB)
#define SMEM_W     65536
#define SMEM_BYTES 131072

__device__ __nv_bfloat16 g_W_hi[O_ * K_TOTAL];
__device__ __nv_bfloat16 g_W_lo[O_ * K_TOTAL];

__global__ void prep_W(const float* __restrict__ base_w,
                       const float* __restrict__ spline_w) {
    int idx = blockIdx.x * blockDim.x + threadIdx.x;
    if (idx >= O_ * K_TOTAL) return;
    int n = idx / K_TOTAL, k = idx - n * K_TOTAL;
    int j = k >> 7, i = k & 127;
    float w = (j == 0) ? base_w[n * D_ + i]
                       : spline_w[(n * D_ + i) * G_ + (j - 1)];
    __nv_bfloat16 hi = __float2bfloat16(w);
    float rem = w - __bfloat162float(hi);
    g_W_hi[idx] = hi;
    g_W_lo[idx] = __float2bfloat16(rem);
}

// ---------------- helpers ----------------
__device__ __forceinline__ uint32_t s2u(const void* p) {
    uint32_t a;
    asm("{ .reg .u64 t; cvta.to.shared.u64 t, %1; cvt.u32.u64 %0, t; }"
        : "=r"(a) : "l"(p));
    return a;
}
#define SWZ(o) ((o) ^ (((o) >> 3) & 0x70))

__device__ __forceinline__ void st32(uint32_t a, uint32_t v) {
    asm volatile("st.shared.b32 [%0], %1;" :: "r"(a), "r"(v) : "memory");
}
__device__ __forceinline__ uint32_t pack2(__nv_bfloat16 a, __nv_bfloat16 b) {
    return (uint32_t)__bfloat16_as_ushort(a) |
           ((uint32_t)__bfloat16_as_ushort(b) << 16);
}
__device__ __forceinline__ void ldsm4(uint32_t* r, uint32_t addr) {
    asm volatile("ldmatrix.sync.aligned.m8n8.x4.shared.b16 {%0,%1,%2,%3}, [%4];"
        : "=r"(r[0]), "=r"(r[1]), "=r"(r[2]), "=r"(r[3]) : "r"(addr));
}
__device__ __forceinline__ void mma16816(float* c, const uint32_t* a,
                                         const uint32_t* b) {
    asm volatile(
        "mma.sync.aligned.m16n8k16.row.col.f32.bf16.bf16.f32 "
        "{%0,%1,%2,%3}, {%4,%5,%6,%7}, {%8,%9}, {%0,%1,%2,%3};"
        : "+f"(c[0]), "+f"(c[1]), "+f"(c[2]), "+f"(c[3])
        : "r"(a[0]), "r"(a[1]), "r"(a[2]), "r"(a[3]), "r"(b[0]), "r"(b[1]));
}

__global__ __launch_bounds__(THREADS, 1)
void kan_hmma_kernel(const float* __restrict__ x,
                     const int* __restrict__ t_indices,
                     const float* __restrict__ time_emb,
                     const float* __restrict__ base_b,
                     float* __restrict__ out) {
    extern __shared__ char smem[];
    const uint32_t sb = s2u(smem);
    const int tid = threadIdx.x, wid = tid >> 5, lane = tid & 31;
    const int m0 = blockIdx.y * BM, o0 = blockIdx.x * BN;
    const int h = (m0 / N_) % H_;
    int ts = t_indices[h];
    ts = min(max(ts, 0), H_ - 1);

    const int warp_m = wid & 3;        // 4 x 32-row tiles
    const int warp_n = wid >> 2;       // 4 x 32-col tiles

    // ---- feature-producer mapping: 4 threads per row, 16 feats/thread/chunk
    const int frow = tid >> 2, quad = tid & 3;
    const float* xrow = x + (size_t)(m0 + frow) * C_;
    const float* emb8 = time_emb + ts * 8;

    // ---- per-lane ldmatrix address components (SW128) ----
    // A (F): per m16 tile t: rows warp_m*32 + t*16 (+8 by lane>>3), k by lane>>4
    const uint32_t kaoff = ((lane >> 4) & 1) * 16;
    uint32_t aB[2], aX[2];
#pragma unroll
    for (int t = 0; t < 2; ++t) {
        int r = warp_m * 32 + t * 16 + ((lane >> 3) & 1) * 8 + (lane & 7);
        aB[t] = r * 128;
        aX[t] = (r & 7) * 16;
    }
    // B (W): per 16-col group ng: rows warp_n*32 + ng*16 (+8 by lane>>4), k by lane>>3
    const uint32_t kboff = ((lane >> 3) & 1) * 16;
    uint32_t bB[2], bX[2];
#pragma unroll
    for (int ng = 0; ng < 2; ++ng) {
        int r = warp_n * 32 + ng * 16 + ((lane >> 4) & 1) * 8 + (lane & 7);
        bB[ng] = r * 128;
        bX[ng] = (r & 7) * 16;
    }

    float acc[2][4][4];                 // [m16 tile][n8 tile][frag]
#pragma unroll
    for (int t = 0; t < 2; ++t)
#pragma unroll
        for (int j = 0; j < 4; ++j)
#pragma unroll
            for (int e = 0; e < 4; ++e) acc[t][j][e] = 0.0f;

    auto issue_W = [&](int kt, int buf) {
        const int k0 = kt * KC;
        const uint32_t wbase = sb + SMEM_W + buf * 32768;
#pragma unroll
        for (int s = 0; s < 4; ++s) {
            int v  = tid + THREADS * s;      // 0..2047 16B-units
            int hl = v >> 10;                // 0: hi, 1: lo
            int r  = (v >> 3) & 127;
            int u  = v & 7;
            const __nv_bfloat16* src =
                (hl ? g_W_lo : g_W_hi) + (size_t)(o0 + r) * K_TOTAL + k0 + u * 8;
            uint32_t dst = wbase + hl * 16384 + SWZ((uint32_t)(r * 128 + u * 16));
            asm volatile("cp.async.cg.shared.global [%0], [%1], 16;"
                         :: "r"(dst), "l"(src));
        }
        asm volatile("cp.async.commit_group;" ::: "memory");
    };

    // Feature slab for chunk kt into buffer buf. 16 features per thread.
    auto do_feats = [&](int kt, int buf) {
        const int jf = kt >> 1;
        const float gc = -1.0f + 0.5f * (float)(jf - 1);
        const int cbase = (kt & 1) * 64 + quad * 4;
        const uint32_t fhi = sb + buf * 32768;
        const uint32_t flo = fhi + 16384;
#pragma unroll
        for (int q = 0; q < 4; ++q) {
            const int c = cbase + q * 16;
            const float4 vv = (c < C_)
                ? *(const float4*)(xrow + c)
                : *(const float4*)(emb8 + (c - C_));
            const float* pv = (const float*)&vv;
            float fv[4];
#pragma unroll
            for (int e = 0; e < 4; ++e) {
                float v = pv[e];
                if (jf == 0) {
                    fv[e] = __fdividef(v, 1.0f + __expf(-v));
                } else {
                    float t = (v - gc) * 2.0f;
                    fv[e] = __expf(-t * t);
                }
            }
            __nv_bfloat16 h0 = __float2bfloat16(fv[0]);
            __nv_bfloat16 h1 = __float2bfloat16(fv[1]);
            __nv_bfloat16 h2 = __float2bfloat16(fv[2]);
            __nv_bfloat16 h3 = __float2bfloat16(fv[3]);
            __nv_bfloat16 l0 = __float2bfloat16(fv[0] - __bfloat162float(h0));
            __nv_bfloat16 l1 = __float2bfloat16(fv[1] - __bfloat162float(h1));
            __nv_bfloat16 l2 = __float2bfloat16(fv[2] - __bfloat162float(h2));
            __nv_bfloat16 l3 = __float2bfloat16(fv[3] - __bfloat162float(h3));
            const int kk = quad * 4 + q * 16;
            uint32_t off = (uint32_t)(frow * 128 + kk * 2);
            uint32_t sa0 = SWZ(off), sa1 = SWZ(off + 4);
            st32(fhi + sa0, pack2(h0, h1));
            st32(fhi + sa1, pack2(h2, h3));
            st32(flo + sa0, pack2(l0, l1));
            st32(flo + sa1, pack2(l2, l3));
        }
    };

    // ---- prologue ----
    issue_W(0, 0);
    do_feats(0, 0);
    asm volatile("cp.async.wait_group 0;" ::: "memory");
    __syncthreads();

    // ---- main loop: one __syncthreads per chunk ----
#pragma unroll 1
    for (int kt = 0; kt < NCHUNK; ++kt) {
        const int b = kt & 1;
        if (kt + 1 < NCHUNK) issue_W(kt + 1, b ^ 1);

        const uint32_t fb = sb + b * 32768;        // F hi
        const uint32_t fl = fb + 16384;            // F lo
        const uint32_t wb = sb + SMEM_W + b * 32768;
        const uint32_t wl = wb + 16384;

#pragma unroll
        for (int s = 0; s < 4; ++s) {
            const uint32_t ka = s * 32 + kaoff;
            const uint32_t kb = s * 32 + kboff;
            uint32_t ah[2][4], al[2][4];
#pragma unroll
            for (int t = 0; t < 2; ++t) {
                ldsm4(ah[t], fb + aB[t] + (ka ^ aX[t]));
                ldsm4(al[t], fl + aB[t] + (ka ^ aX[t]));
            }
#pragma unroll
            for (int ng = 0; ng < 2; ++ng) {
                uint32_t bh[4], bl[4];
                ldsm4(bh, wb + bB[ng] + (kb ^ bX[ng]));
                ldsm4(bl, wl + bB[ng] + (kb ^ bX[ng]));
                // bh/bl: {r0,r1} -> n8 tile ng*2, {r2,r3} -> tile ng*2+1
#pragma unroll
                for (int t = 0; t < 2; ++t) {
                    mma16816(acc[t][ng * 2 + 0], ah[t], bh + 0);
                    mma16816(acc[t][ng * 2 + 0], ah[t], bl + 0);
                    mma16816(acc[t][ng * 2 + 0], al[t], bh + 0);
                    mma16816(acc[t][ng * 2 + 1], ah[t], bh + 2);
                    mma16816(acc[t][ng * 2 + 1], ah[t], bl + 2);
                    mma16816(acc[t][ng * 2 + 1], al[t], bh + 2);
                }
            }
        }

        if (kt + 1 < NCHUNK) do_feats(kt + 1, b ^ 1);
        asm volatile("cp.async.wait_group 0;" ::: "memory");
        __syncthreads();
    }

    // ---- epilogue: + bias, float2 stores ----
    {
        const float* bb = base_b + o0 + warp_n * 32;
        float2 bi[4];
#pragma unroll
        for (int j = 0; j < 4; ++j)
            bi[j] = *(const float2*)(bb + j * 8 + (lane & 3) * 2);
#pragma unroll
        for (int t = 0; t < 2; ++t) {
            int r0 = m0 + warp_m * 32 + t * 16 + (lane >> 2);
            float* p0 = out + (size_t)r0 * O_ + o0 + warp_n * 32;
            float* p1 = p0 + (size_t)8 * O_;
#pragma unroll
            for (int j = 0; j < 4; ++j) {
                int col = j * 8 + (lane & 3) * 2;
                float2 v0, v1;
                v0.x = acc[t][j][0] + bi[j].x;
                v0.y = acc[t][j][1] + bi[j].y;
                v1.x = acc[t][j][2] + bi[j].x;
                v1.y = acc[t][j][3] + bi[j].y;
                *(float2*)(p0 + col) = v0;
                *(float2*)(p1 + col) = v1;
            }
        }
    }
}

extern "C" void kernel_launch(void* const* d_in, const int* in_sizes, int n_in,
                              void* d_out, int out_size) {
    const float* x         = (const float*)d_in[0];
    const int*   t_indices = (const int*)d_in[1];   // int32 (JAX x64 disabled)
    const float* time_emb  = (const float*)d_in[2];
    const float* base_w    = (const float*)d_in[3];
    const float* base_b    = (const float*)d_in[4];
    const float* spline_w  = (const float*)d_in[5];
    float* out = (float*)d_out;

    {
        int total = O_ * K_TOTAL;
        prep_W<<<(total + 255) / 256, 256>>>(base_w, spline_w);
    }

    cudaFuncSetAttribute(kan_hmma_kernel,
                         cudaFuncAttributeMaxDynamicSharedMemorySize, SMEM_BYTES);
    dim3 grid(O_ / BN, M_TOTAL / BM);   // (4, 384) = 1536 CTAs
    kan_hmma_kernel<<<grid, THREADS, SMEM_BYTES>>>(x, t_indices, time_emb,
                                                   base_b, out);
}

// round 9
// speedup vs baseline: 1.7401x; 1.7401x over previous
#include <cuda_runtime.h>
#include <cuda_fp16.h>
#include <cstdint>

// ---------------------------------------------------------------------------
// TimeAwareKAN via single GEMM  out[m,o] = sum_k F[m,k] * W[o,k] + b[o]
//   M = 49152, K = 768 (6 families x 128), O = 512
//   family j==0: silu(x_in); j=1..5: exp(-(2*(x_in - g_{j-1}))^2)
// compute_103 toolchain => no tcgen05. Warp-level HMMA m16n8k16.
// R8 finding: 3-product bf16 split wastes 3x MMA for 5.6e-6 accuracy vs 1e-3
// bar. This round: SINGLE-product fp16 (u=4.9e-4 -> L2 rel_err ~3-5e-4),
// 1/3 the MMA work, half the smem traffic.
// t_indices is int32 on device (JAX x64 disabled).
// ---------------------------------------------------------------------------

#define B_   4
#define H_   24
#define N_   512
#define C_   120
#define D_   128
#define O_   512
#define G_   5
#define M_TOTAL (B_ * H_ * N_)
#define K_TOTAL 768

#define BM 128
#define BN 128
#define KC 64                    // 64 fp16 = 128B rows -> SW128 native
#define NCHUNK (K_TOTAL / KC)    // 12
#define THREADS 512

// SMEM: F bufs 2 x 16KB at 0; W bufs 2 x 16KB at 32768
#define SMEM_W     32768
#define SMEM_BYTES 65536

__device__ __half g_W_h[O_ * K_TOTAL];

__global__ void prep_W(const float* __restrict__ base_w,
                       const float* __restrict__ spline_w) {
    int idx = blockIdx.x * blockDim.x + threadIdx.x;
    if (idx >= O_ * K_TOTAL) return;
    int n = idx / K_TOTAL, k = idx - n * K_TOTAL;
    int j = k >> 7, i = k & 127;
    float w = (j == 0) ? base_w[n * D_ + i]
                       : spline_w[(n * D_ + i) * G_ + (j - 1)];
    g_W_h[idx] = __float2half(w);
}

// ---------------- helpers ----------------
__device__ __forceinline__ uint32_t s2u(const void* p) {
    uint32_t a;
    asm("{ .reg .u64 t; cvta.to.shared.u64 t, %1; cvt.u32.u64 %0, t; }"
        : "=r"(a) : "l"(p));
    return a;
}
#define SWZ(o) ((o) ^ (((o) >> 3) & 0x70))

__device__ __forceinline__ void st32(uint32_t a, uint32_t v) {
    asm volatile("st.shared.b32 [%0], %1;" :: "r"(a), "r"(v) : "memory");
}
__device__ __forceinline__ uint32_t pack2h(__half a, __half b) {
    return (uint32_t)__half_as_ushort(a) |
           ((uint32_t)__half_as_ushort(b) << 16);
}
__device__ __forceinline__ void ldsm4(uint32_t* r, uint32_t addr) {
    asm volatile("ldmatrix.sync.aligned.m8n8.x4.shared.b16 {%0,%1,%2,%3}, [%4];"
        : "=r"(r[0]), "=r"(r[1]), "=r"(r[2]), "=r"(r[3]) : "r"(addr));
}
__device__ __forceinline__ void mma16816(float* c, const uint32_t* a,
                                         const uint32_t* b) {
    asm volatile(
        "mma.sync.aligned.m16n8k16.row.col.f32.f16.f16.f32 "
        "{%0,%1,%2,%3}, {%4,%5,%6,%7}, {%8,%9}, {%0,%1,%2,%3};"
        : "+f"(c[0]), "+f"(c[1]), "+f"(c[2]), "+f"(c[3])
        : "r"(a[0]), "r"(a[1]), "r"(a[2]), "r"(a[3]), "r"(b[0]), "r"(b[1]));
}

__global__ __launch_bounds__(THREADS, 1)
void kan_hmma_kernel(const float* __restrict__ x,
                     const int* __restrict__ t_indices,
                     const float* __restrict__ time_emb,
                     const float* __restrict__ base_b,
                     float* __restrict__ out) {
    extern __shared__ char smem[];
    const uint32_t sb = s2u(smem);
    const int tid = threadIdx.x, wid = tid >> 5, lane = tid & 31;
    const int m0 = blockIdx.y * BM, o0 = blockIdx.x * BN;
    const int h = (m0 / N_) % H_;
    int ts = t_indices[h];
    ts = min(max(ts, 0), H_ - 1);

    const int warp_m = wid & 3;        // 4 x 32-row tiles
    const int warp_n = wid >> 2;       // 4 x 32-col tiles

    // ---- feature-producer mapping: 4 threads per row, 16 feats/thread/chunk
    const int frow = tid >> 2, quad = tid & 3;
    const float* xrow = x + (size_t)(m0 + frow) * C_;
    const float* emb8 = time_emb + ts * 8;

    // ---- per-lane ldmatrix address components (SW128) ----
    const uint32_t kaoff = ((lane >> 4) & 1) * 16;
    uint32_t aB[2], aX[2];
#pragma unroll
    for (int t = 0; t < 2; ++t) {
        int r = warp_m * 32 + t * 16 + ((lane >> 3) & 1) * 8 + (lane & 7);
        aB[t] = r * 128;
        aX[t] = (r & 7) * 16;
    }
    const uint32_t kboff = ((lane >> 3) & 1) * 16;
    uint32_t bB[2], bX[2];
#pragma unroll
    for (int ng = 0; ng < 2; ++ng) {
        int r = warp_n * 32 + ng * 16 + ((lane >> 4) & 1) * 8 + (lane & 7);
        bB[ng] = r * 128;
        bX[ng] = (r & 7) * 16;
    }

    float acc[2][4][4];                 // [m16 tile][n8 tile][frag]
#pragma unroll
    for (int t = 0; t < 2; ++t)
#pragma unroll
        for (int j = 0; j < 4; ++j)
#pragma unroll
            for (int e = 0; e < 4; ++e) acc[t][j][e] = 0.0f;

    auto issue_W = [&](int kt, int buf) {
        const int k0 = kt * KC;
        const uint32_t wbase = sb + SMEM_W + buf * 16384;
#pragma unroll
        for (int s = 0; s < 2; ++s) {
            int v  = tid + THREADS * s;      // 0..1023 16B-units
            int r  = v >> 3;                 // 0..127
            int u  = v & 7;
            const __half* src =
                g_W_h + (size_t)(o0 + r) * K_TOTAL + k0 + u * 8;
            uint32_t dst = wbase + SWZ((uint32_t)(r * 128 + u * 16));
            asm volatile("cp.async.cg.shared.global [%0], [%1], 16;"
                         :: "r"(dst), "l"(src));
        }
        asm volatile("cp.async.commit_group;" ::: "memory");
    };

    // Feature slab for chunk kt into buffer buf. 16 features per thread.
    auto do_feats = [&](int kt, int buf) {
        const int jf = kt >> 1;
        const float gc = -1.0f + 0.5f * (float)(jf - 1);
        const int cbase = (kt & 1) * 64 + quad * 4;
        const uint32_t fhi = sb + buf * 16384;
#pragma unroll
        for (int q = 0; q < 4; ++q) {
            const int c = cbase + q * 16;
            const float4 vv = (c < C_)
                ? *(const float4*)(xrow + c)
                : *(const float4*)(emb8 + (c - C_));
            const float* pv = (const float*)&vv;
            float fv[4];
#pragma unroll
            for (int e = 0; e < 4; ++e) {
                float v = pv[e];
                if (jf == 0) {
                    fv[e] = __fdividef(v, 1.0f + __expf(-v));
                } else {
                    float t = (v - gc) * 2.0f;
                    fv[e] = __expf(-t * t);
                }
            }
            const int kk = quad * 4 + q * 16;
            uint32_t off = (uint32_t)(frow * 128 + kk * 2);
            st32(fhi + SWZ(off),     pack2h(__float2half(fv[0]), __float2half(fv[1])));
            st32(fhi + SWZ(off + 4), pack2h(__float2half(fv[2]), __float2half(fv[3])));
        }
    };

    // ---- prologue ----
    issue_W(0, 0);
    do_feats(0, 0);
    asm volatile("cp.async.wait_group 0;" ::: "memory");
    __syncthreads();

    // ---- main loop: one __syncthreads per chunk ----
#pragma unroll 1
    for (int kt = 0; kt < NCHUNK; ++kt) {
        const int b = kt & 1;
        if (kt + 1 < NCHUNK) issue_W(kt + 1, b ^ 1);

        const uint32_t fb = sb + b * 16384;            // F
        const uint32_t wb = sb + SMEM_W + b * 16384;   // W

#pragma unroll
        for (int s = 0; s < 4; ++s) {
            const uint32_t ka = s * 32 + kaoff;
            const uint32_t kb = s * 32 + kboff;
            uint32_t ah[2][4];
#pragma unroll
            for (int t = 0; t < 2; ++t)
                ldsm4(ah[t], fb + aB[t] + (ka ^ aX[t]));
#pragma unroll
            for (int ng = 0; ng < 2; ++ng) {
                uint32_t bh[4];
                ldsm4(bh, wb + bB[ng] + (kb ^ bX[ng]));
                // bh: {r0,r1} -> n8 tile ng*2, {r2,r3} -> tile ng*2+1
#pragma unroll
                for (int t = 0; t < 2; ++t) {
                    mma16816(acc[t][ng * 2 + 0], ah[t], bh + 0);
                    mma16816(acc[t][ng * 2 + 1], ah[t], bh + 2);
                }
            }
        }

        if (kt + 1 < NCHUNK) do_feats(kt + 1, b ^ 1);
        asm volatile("cp.async.wait_group 0;" ::: "memory");
        __syncthreads();
    }

    // ---- epilogue: + bias, float2 stores ----
    {
        const float* bb = base_b + o0 + warp_n * 32;
        float2 bi[4];
#pragma unroll
        for (int j = 0; j < 4; ++j)
            bi[j] = *(const float2*)(bb + j * 8 + (lane & 3) * 2);
#pragma unroll
        for (int t = 0; t < 2; ++t) {
            int r0 = m0 + warp_m * 32 + t * 16 + (lane >> 2);
            float* p0 = out + (size_t)r0 * O_ + o0 + warp_n * 32;
            float* p1 = p0 + (size_t)8 * O_;
#pragma unroll
            for (int j = 0; j < 4; ++j) {
                int col = j * 8 + (lane & 3) * 2;
                float2 v0, v1;
                v0.x = acc[t][j][0] + bi[j].x;
                v0.y = acc[t][j][1] + bi[j].y;
                v1.x = acc[t][j][2] + bi[j].x;
                v1.y = acc[t][j][3] + bi[j].y;
                *(float2*)(p0 + col) = v0;
                *(float2*)(p1 + col) = v1;
            }
        }
    }
}

extern "C" void kernel_launch(void* const* d_in, const int* in_sizes, int n_in,
                              void* d_out, int out_size) {
    const float* x         = (const float*)d_in[0];
    const int*   t_indices = (const int*)d_in[1];   // int32 (JAX x64 disabled)
    const float* time_emb  = (const float*)d_in[2];
    const float* base_w    = (const float*)d_in[3];
    const float* base_b    = (const float*)d_in[4];
    const float* spline_w  = (const float*)d_in[5];
    float* out = (float*)d_out;

    {
        int total = O_ * K_TOTAL;
        prep_W<<<(total + 255) / 256, 256>>>(base_w, spline_w);
    }

    cudaFuncSetAttribute(kan_hmma_kernel,
                         cudaFuncAttributeMaxDynamicSharedMemorySize, SMEM_BYTES);
    dim3 grid(O_ / BN, M_TOTAL / BM);   // (4, 384) = 1536 CTAs
    kan_hmma_kernel<<<grid, THREADS, SMEM_BYTES>>>(x, t_indices, time_emb,
                                                   base_b, out);
}

// round 10
// speedup vs baseline: 1.7824x; 1.0243x over previous
#include <cuda_runtime.h>
#include <cuda_fp16.h>
#include <cstdint>

// ---------------------------------------------------------------------------
// TimeAwareKAN via single GEMM  out[m,o] = sum_k F[m,k] * W[o,k] + b[o]
//   M = 49152, K = 768 (6 families x 128), O = 512
// R9: decouple. Kernel 1 materializes F (fp16) once to gmem (removes the 4x
// redundant in-GEMM feature path that capped R8 at tensor=28%). Kernel 2 is a
// pure cp.async + ldmatrix + HMMA m16n8k16 streaming GEMM, BN=256.
// t_indices is int32 on device (JAX x64 disabled).
// ---------------------------------------------------------------------------

#define B_   4
#define H_   24
#define N_   512
#define C_   120
#define D_   128
#define O_   512
#define G_   5
#define M_TOTAL (B_ * H_ * N_)
#define K_TOTAL 768

#define BM 128
#define BN 256
#define KC 64                    // 64 fp16 = 128B rows -> SW128 native
#define NCHUNK (K_TOTAL / KC)    // 12
#define THREADS 512

// SMEM: F bufs 2 x 16KB at 0; W bufs 2 x 32KB at 32768
#define SMEM_W     32768
#define SMEM_BYTES 98304

__device__ __half g_W_h[O_ * K_TOTAL];            // 0.75 MB
__device__ __half g_F[(size_t)M_TOTAL * K_TOTAL]; // 75.5 MB scratch

__global__ void prep_W(const float* __restrict__ base_w,
                       const float* __restrict__ spline_w) {
    int idx = blockIdx.x * blockDim.x + threadIdx.x;
    if (idx >= O_ * K_TOTAL) return;
    int n = idx / K_TOTAL, k = idx - n * K_TOTAL;
    int j = k >> 7, i = k & 127;
    float w = (j == 0) ? base_w[n * D_ + i]
                       : spline_w[(n * D_ + i) * G_ + (j - 1)];
    g_W_h[idx] = __float2half(w);
}

// ---- Feature kernel: one thread -> 8 contiguous k of one row ----
__global__ __launch_bounds__(512)
void feat_kernel(const float* __restrict__ x,
                 const int* __restrict__ t_indices,
                 const float* __restrict__ time_emb) {
    int g = blockIdx.x * 512 + threadIdx.x;        // < M*96
    int m = g / 96, c8 = g - m * 96;
    int j = c8 >> 4, i0 = (c8 & 15) * 8;

    float4 a, b;
    if (i0 < C_) {
        a = *(const float4*)(x + (size_t)m * C_ + i0);
        b = *(const float4*)(x + (size_t)m * C_ + i0 + 4);
    } else {                                       // i0 == 120: time emb
        int h = (m >> 9) % H_;
        int ts = t_indices[h];
        ts = min(max(ts, 0), H_ - 1);
        a = *(const float4*)(time_emb + ts * 8);
        b = *(const float4*)(time_emb + ts * 8 + 4);
    }
    float v[8] = {a.x, a.y, a.z, a.w, b.x, b.y, b.z, b.w};
    float f[8];
    if (j == 0) {
#pragma unroll
        for (int e = 0; e < 8; ++e)
            f[e] = __fdividef(v[e], 1.0f + __expf(-v[e]));
    } else {
        const float gc = -1.0f + 0.5f * (float)(j - 1);
#pragma unroll
        for (int e = 0; e < 8; ++e) {
            float t = (v[e] - gc) * 2.0f;
            f[e] = __expf(-t * t);
        }
    }
    __half2 h0 = __floats2half2_rn(f[0], f[1]);
    __half2 h1 = __floats2half2_rn(f[2], f[3]);
    __half2 h2 = __floats2half2_rn(f[4], f[5]);
    __half2 h3 = __floats2half2_rn(f[6], f[7]);
    uint4 o;
    o.x = *(uint32_t*)&h0; o.y = *(uint32_t*)&h1;
    o.z = *(uint32_t*)&h2; o.w = *(uint32_t*)&h3;
    *(uint4*)(g_F + (size_t)m * K_TOTAL + j * 128 + i0) = o;
}

// ---------------- helpers ----------------
__device__ __forceinline__ uint32_t s2u(const void* p) {
    uint32_t a;
    asm("{ .reg .u64 t; cvta.to.shared.u64 t, %1; cvt.u32.u64 %0, t; }"
        : "=r"(a) : "l"(p));
    return a;
}
#define SWZ(o) ((o) ^ (((o) >> 3) & 0x70))

__device__ __forceinline__ void ldsm4(uint32_t* r, uint32_t addr) {
    asm volatile("ldmatrix.sync.aligned.m8n8.x4.shared.b16 {%0,%1,%2,%3}, [%4];"
        : "=r"(r[0]), "=r"(r[1]), "=r"(r[2]), "=r"(r[3]) : "r"(addr));
}
__device__ __forceinline__ void mma16816(float* c, const uint32_t* a,
                                         const uint32_t* b) {
    asm volatile(
        "mma.sync.aligned.m16n8k16.row.col.f32.f16.f16.f32 "
        "{%0,%1,%2,%3}, {%4,%5,%6,%7}, {%8,%9}, {%0,%1,%2,%3};"
        : "+f"(c[0]), "+f"(c[1]), "+f"(c[2]), "+f"(c[3])
        : "r"(a[0]), "r"(a[1]), "r"(a[2]), "r"(a[3]), "r"(b[0]), "r"(b[1]));
}

__global__ __launch_bounds__(THREADS, 1)
void kan_hmma_kernel(const float* __restrict__ base_b,
                     float* __restrict__ out) {
    extern __shared__ char smem[];
    const uint32_t sb = s2u(smem);
    const int tid = threadIdx.x, wid = tid >> 5, lane = tid & 31;
    const int m0 = blockIdx.y * BM, o0 = blockIdx.x * BN;

    const int warp_m = wid & 3;        // 4 x 32-row tiles
    const int warp_n = wid >> 2;       // 4 x 64-col tiles

    // ---- per-lane ldmatrix address components (SW128) ----
    const uint32_t kaoff = ((lane >> 4) & 1) * 16;
    uint32_t aB[2], aX[2];
#pragma unroll
    for (int t = 0; t < 2; ++t) {
        int r = warp_m * 32 + t * 16 + ((lane >> 3) & 1) * 8 + (lane & 7);
        aB[t] = r * 128;
        aX[t] = (r & 7) * 16;
    }
    const uint32_t kboff = ((lane >> 3) & 1) * 16;
    uint32_t bB[4], bX[4];
#pragma unroll
    for (int ng = 0; ng < 4; ++ng) {
        int r = warp_n * 64 + ng * 16 + ((lane >> 4) & 1) * 8 + (lane & 7);
        bB[ng] = r * 128;
        bX[ng] = (r & 7) * 16;
    }

    float acc[2][8][4];                 // [m16 tile][n8 tile][frag]
#pragma unroll
    for (int t = 0; t < 2; ++t)
#pragma unroll
        for (int j = 0; j < 8; ++j)
#pragma unroll
            for (int e = 0; e < 4; ++e) acc[t][j][e] = 0.0f;

    auto issue_chunk = [&](int kt, int buf) {
        const int k0 = kt * KC;
        // F: 128 rows x 8 units = 1024
        {
            const uint32_t fbase = sb + buf * 16384;
#pragma unroll
            for (int s = 0; s < 2; ++s) {
                int v = tid + THREADS * s;
                int r = v >> 3, u = v & 7;
                const __half* src =
                    g_F + (size_t)(m0 + r) * K_TOTAL + k0 + u * 8;
                uint32_t dst = fbase + SWZ((uint32_t)(r * 128 + u * 16));
                asm volatile("cp.async.cg.shared.global [%0], [%1], 16;"
                             :: "r"(dst), "l"(src));
            }
        }
        // W: 256 rows x 8 units = 2048
        {
            const uint32_t wbase = sb + SMEM_W + buf * 32768;
#pragma unroll
            for (int s = 0; s < 4; ++s) {
                int v = tid + THREADS * s;
                int r = v >> 3, u = v & 7;
                const __half* src =
                    g_W_h + (size_t)(o0 + r) * K_TOTAL + k0 + u * 8;
                uint32_t dst = wbase + SWZ((uint32_t)(r * 128 + u * 16));
                asm volatile("cp.async.cg.shared.global [%0], [%1], 16;"
                             :: "r"(dst), "l"(src));
            }
        }
        asm volatile("cp.async.commit_group;" ::: "memory");
    };

    // ---- prologue ----
    issue_chunk(0, 0);
    asm volatile("cp.async.wait_group 0;" ::: "memory");
    __syncthreads();

    // ---- main loop ----
#pragma unroll 1
    for (int kt = 0; kt < NCHUNK; ++kt) {
        const int b = kt & 1;
        if (kt + 1 < NCHUNK) issue_chunk(kt + 1, b ^ 1);

        const uint32_t fb = sb + b * 16384;            // F
        const uint32_t wb = sb + SMEM_W + b * 32768;   // W

#pragma unroll
        for (int s = 0; s < 4; ++s) {
            const uint32_t ka = s * 32 + kaoff;
            const uint32_t kb = s * 32 + kboff;
            uint32_t ah[2][4];
#pragma unroll
            for (int t = 0; t < 2; ++t)
                ldsm4(ah[t], fb + aB[t] + (ka ^ aX[t]));
#pragma unroll
            for (int ng = 0; ng < 4; ++ng) {
                uint32_t bh[4];
                ldsm4(bh, wb + bB[ng] + (kb ^ bX[ng]));
                // bh: {r0,r1} -> n8 tile ng*2, {r2,r3} -> tile ng*2+1
#pragma unroll
                for (int t = 0; t < 2; ++t) {
                    mma16816(acc[t][ng * 2 + 0], ah[t], bh + 0);
                    mma16816(acc[t][ng * 2 + 1], ah[t], bh + 2);
                }
            }
        }

        asm volatile("cp.async.wait_group 0;" ::: "memory");
        __syncthreads();
    }

    // ---- epilogue: + bias, float2 stores ----
    {
        const float* bb = base_b + o0 + warp_n * 64;
        float2 bi[8];
#pragma unroll
        for (int j = 0; j < 8; ++j)
            bi[j] = *(const float2*)(bb + j * 8 + (lane & 3) * 2);
#pragma unroll
        for (int t = 0; t < 2; ++t) {
            int r0 = m0 + warp_m * 32 + t * 16 + (lane >> 2);
            float* p0 = out + (size_t)r0 * O_ + o0 + warp_n * 64;
            float* p1 = p0 + (size_t)8 * O_;
#pragma unroll
            for (int j = 0; j < 8; ++j) {
                int col = j * 8 + (lane & 3) * 2;
                float2 v0, v1;
                v0.x = acc[t][j][0] + bi[j].x;
                v0.y = acc[t][j][1] + bi[j].y;
                v1.x = acc[t][j][2] + bi[j].x;
                v1.y = acc[t][j][3] + bi[j].y;
                *(float2*)(p0 + col) = v0;
                *(float2*)(p1 + col) = v1;
            }
        }
    }
}

extern "C" void kernel_launch(void* const* d_in, const int* in_sizes, int n_in,
                              void* d_out, int out_size) {
    const float* x         = (const float*)d_in[0];
    const int*   t_indices = (const int*)d_in[1];   // int32 (JAX x64 disabled)
    const float* time_emb  = (const float*)d_in[2];
    const float* base_w    = (const float*)d_in[3];
    const float* base_b    = (const float*)d_in[4];
    const float* spline_w  = (const float*)d_in[5];
    float* out = (float*)d_out;

    {
        int total = O_ * K_TOTAL;
        prep_W<<<(total + 255) / 256, 256>>>(base_w, spline_w);
    }
    // Materialize F once: M*96 8-wide groups, 512 thr/blk
    feat_kernel<<<(M_TOTAL * 96) / 512, 512>>>(x, t_indices, time_emb);

    cudaFuncSetAttribute(kan_hmma_kernel,
                         cudaFuncAttributeMaxDynamicSharedMemorySize, SMEM_BYTES);
    dim3 grid(O_ / BN, M_TOTAL / BM);   // (2, 384) = 768 CTAs
    kan_hmma_kernel<<<grid, THREADS, SMEM_BYTES>>>(base_b, out);
}

// round 11
// speedup vs baseline: 2.5850x; 1.4503x over previous
#include <cuda_runtime.h>
#include <cuda_fp16.h>
#include <cstdint>

// ---------------------------------------------------------------------------
// TimeAwareKAN via single GEMM  out[m,o] = sum_k F[m,k] * W[o,k] + b[o]
//   M = 49152, K = 768 (6 families x 128), O = 512
// R10: pure-GEMM restructure. R9 showed hoisting features changed nothing ->
// the chunk-lockstep loop was the bottleneck. Now: 64x64 warp tiles (128 B
// LDS per mma, 32 indep accumulators), 4-stage cp.async pipeline with
// wait_group 2 (empty commit groups at tail), 8 warps/CTA, 1 CTA/SM.
// t_indices is int32 on device (JAX x64 disabled).
// ---------------------------------------------------------------------------

#define B_   4
#define H_   24
#define N_   512
#define C_   120
#define D_   128
#define O_   512
#define G_   5
#define M_TOTAL (B_ * H_ * N_)
#define K_TOTAL 768

#define BM 128
#define BN 256
#define KC 64                    // 64 fp16 = 128B rows -> SW128 native
#define NCHUNK (K_TOTAL / KC)    // 12
#define THREADS 256
#define NSTAGE 4

// Per stage: F 16KB + W 32KB = 48KB. 4 stages = 192KB.
#define STAGE_BYTES 49152
#define SMEM_BYTES  (NSTAGE * STAGE_BYTES)

__device__ __half g_W_h[O_ * K_TOTAL];            // 0.75 MB
__device__ __half g_F[(size_t)M_TOTAL * K_TOTAL]; // 75.5 MB scratch

__global__ void prep_W(const float* __restrict__ base_w,
                       const float* __restrict__ spline_w) {
    int idx = blockIdx.x * blockDim.x + threadIdx.x;
    if (idx >= O_ * K_TOTAL) return;
    int n = idx / K_TOTAL, k = idx - n * K_TOTAL;
    int j = k >> 7, i = k & 127;
    float w = (j == 0) ? base_w[n * D_ + i]
                       : spline_w[(n * D_ + i) * G_ + (j - 1)];
    g_W_h[idx] = __float2half(w);
}

// ---- Feature kernel: one thread -> 8 contiguous k of one row ----
__global__ __launch_bounds__(512)
void feat_kernel(const float* __restrict__ x,
                 const int* __restrict__ t_indices,
                 const float* __restrict__ time_emb) {
    int g = blockIdx.x * 512 + threadIdx.x;        // < M*96
    int m = g / 96, c8 = g - m * 96;
    int j = c8 >> 4, i0 = (c8 & 15) * 8;

    float4 a, b;
    if (i0 < C_) {
        a = *(const float4*)(x + (size_t)m * C_ + i0);
        b = *(const float4*)(x + (size_t)m * C_ + i0 + 4);
    } else {                                       // i0 == 120: time emb
        int h = (m >> 9) % H_;
        int ts = t_indices[h];
        ts = min(max(ts, 0), H_ - 1);
        a = *(const float4*)(time_emb + ts * 8);
        b = *(const float4*)(time_emb + ts * 8 + 4);
    }
    float v[8] = {a.x, a.y, a.z, a.w, b.x, b.y, b.z, b.w};
    float f[8];
    if (j == 0) {
#pragma unroll
        for (int e = 0; e < 8; ++e)
            f[e] = __fdividef(v[e], 1.0f + __expf(-v[e]));
    } else {
        const float gc = -1.0f + 0.5f * (float)(j - 1);
#pragma unroll
        for (int e = 0; e < 8; ++e) {
            float t = (v[e] - gc) * 2.0f;
            f[e] = __expf(-t * t);
        }
    }
    __half2 h0 = __floats2half2_rn(f[0], f[1]);
    __half2 h1 = __floats2half2_rn(f[2], f[3]);
    __half2 h2 = __floats2half2_rn(f[4], f[5]);
    __half2 h3 = __floats2half2_rn(f[6], f[7]);
    uint4 o;
    o.x = *(uint32_t*)&h0; o.y = *(uint32_t*)&h1;
    o.z = *(uint32_t*)&h2; o.w = *(uint32_t*)&h3;
    *(uint4*)(g_F + (size_t)m * K_TOTAL + j * 128 + i0) = o;
}

// ---------------- helpers ----------------
__device__ __forceinline__ uint32_t s2u(const void* p) {
    uint32_t a;
    asm("{ .reg .u64 t; cvta.to.shared.u64 t, %1; cvt.u32.u64 %0, t; }"
        : "=r"(a) : "l"(p));
    return a;
}
#define SWZ(o) ((o) ^ (((o) >> 3) & 0x70))

__device__ __forceinline__ void ldsm4(uint32_t* r, uint32_t addr) {
    asm volatile("ldmatrix.sync.aligned.m8n8.x4.shared.b16 {%0,%1,%2,%3}, [%4];"
        : "=r"(r[0]), "=r"(r[1]), "=r"(r[2]), "=r"(r[3]) : "r"(addr));
}
__device__ __forceinline__ void mma16816(float* c, const uint32_t* a,
                                         const uint32_t* b) {
    asm volatile(
        "mma.sync.aligned.m16n8k16.row.col.f32.f16.f16.f32 "
        "{%0,%1,%2,%3}, {%4,%5,%6,%7}, {%8,%9}, {%0,%1,%2,%3};"
        : "+f"(c[0]), "+f"(c[1]), "+f"(c[2]), "+f"(c[3])
        : "r"(a[0]), "r"(a[1]), "r"(a[2]), "r"(a[3]), "r"(b[0]), "r"(b[1]));
}

__global__ __launch_bounds__(THREADS, 1)
void kan_hmma_kernel(const float* __restrict__ base_b,
                     float* __restrict__ out) {
    extern __shared__ char smem[];
    const uint32_t sb = s2u(smem);
    const int tid = threadIdx.x, wid = tid >> 5, lane = tid & 31;
    const int m0 = blockIdx.y * BM, o0 = blockIdx.x * BN;

    const int warp_m = wid & 1;        // 2 x 64-row tiles
    const int warp_n = wid >> 1;       // 4 x 64-col tiles

    // ---- per-lane ldmatrix address components (SW128) ----
    const uint32_t kaoff = ((lane >> 4) & 1) * 16;
    uint32_t aB[4], aX[4];
#pragma unroll
    for (int t = 0; t < 4; ++t) {
        int r = warp_m * 64 + t * 16 + ((lane >> 3) & 1) * 8 + (lane & 7);
        aB[t] = r * 128;
        aX[t] = (r & 7) * 16;
    }
    const uint32_t kboff = ((lane >> 3) & 1) * 16;
    uint32_t bB[4], bX[4];
#pragma unroll
    for (int ng = 0; ng < 4; ++ng) {
        int r = warp_n * 64 + ng * 16 + ((lane >> 4) & 1) * 8 + (lane & 7);
        bB[ng] = r * 128;
        bX[ng] = (r & 7) * 16;
    }

    float acc[4][8][4];                 // [m16 tile][n8 tile][frag] = 128 regs
#pragma unroll
    for (int t = 0; t < 4; ++t)
#pragma unroll
        for (int j = 0; j < 8; ++j)
#pragma unroll
            for (int e = 0; e < 4; ++e) acc[t][j][e] = 0.0f;

    auto issue_chunk = [&](int kt) {
        const int stage = kt % NSTAGE;
        const int k0 = kt * KC;
        const uint32_t fbase = sb + stage * STAGE_BYTES;
        const uint32_t wbase = fbase + 16384;
        // F: 128 rows x 8 units = 1024 -> 4/thread
#pragma unroll
        for (int s = 0; s < 4; ++s) {
            int v = tid + THREADS * s;
            int r = v >> 3, u = v & 7;
            const __half* src = g_F + (size_t)(m0 + r) * K_TOTAL + k0 + u * 8;
            uint32_t dst = fbase + SWZ((uint32_t)(r * 128 + u * 16));
            asm volatile("cp.async.cg.shared.global [%0], [%1], 16;"
                         :: "r"(dst), "l"(src));
        }
        // W: 256 rows x 8 units = 2048 -> 8/thread
#pragma unroll
        for (int s = 0; s < 8; ++s) {
            int v = tid + THREADS * s;
            int r = v >> 3, u = v & 7;
            const __half* src = g_W_h + (size_t)(o0 + r) * K_TOTAL + k0 + u * 8;
            uint32_t dst = wbase + SWZ((uint32_t)(r * 128 + u * 16));
            asm volatile("cp.async.cg.shared.global [%0], [%1], 16;"
                         :: "r"(dst), "l"(src));
        }
        asm volatile("cp.async.commit_group;" ::: "memory");
    };

    // ---- prologue: fill 3 stages ----
    issue_chunk(0);
    issue_chunk(1);
    issue_chunk(2);
    asm volatile("cp.async.wait_group 2;" ::: "memory");
    __syncthreads();

    // ---- main loop: exactly one commit group per iteration ----
#pragma unroll 1
    for (int kt = 0; kt < NCHUNK; ++kt) {
        if (kt + 3 < NCHUNK) {
            issue_chunk(kt + 3);
        } else {
            asm volatile("cp.async.commit_group;" ::: "memory");  // empty group
        }

        const uint32_t fb = sb + (kt % NSTAGE) * STAGE_BYTES;
        const uint32_t wb = fb + 16384;

#pragma unroll
        for (int s = 0; s < 4; ++s) {
            const uint32_t ka = s * 32 + kaoff;
            const uint32_t kb = s * 32 + kboff;
            uint32_t ah[4][4];
#pragma unroll
            for (int t = 0; t < 4; ++t)
                ldsm4(ah[t], fb + aB[t] + (ka ^ aX[t]));
#pragma unroll
            for (int ng = 0; ng < 4; ++ng) {
                uint32_t bh[4];
                ldsm4(bh, wb + bB[ng] + (kb ^ bX[ng]));
                // bh: {r0,r1} -> n8 tile ng*2, {r2,r3} -> tile ng*2+1
#pragma unroll
                for (int t = 0; t < 4; ++t) {
                    mma16816(acc[t][ng * 2 + 0], ah[t], bh + 0);
                    mma16816(acc[t][ng * 2 + 1], ah[t], bh + 2);
                }
            }
        }

        // oldest of the 3 pending groups (chunk kt+1) must be done
        asm volatile("cp.async.wait_group 2;" ::: "memory");
        __syncthreads();
    }

    // ---- epilogue: + bias, float2 stores ----
    {
        const float* bb = base_b + o0 + warp_n * 64;
        float2 bi[8];
#pragma unroll
        for (int j = 0; j < 8; ++j)
            bi[j] = *(const float2*)(bb + j * 8 + (lane & 3) * 2);
#pragma unroll
        for (int t = 0; t < 4; ++t) {
            int r0 = m0 + warp_m * 64 + t * 16 + (lane >> 2);
            float* p0 = out + (size_t)r0 * O_ + o0 + warp_n * 64;
            float* p1 = p0 + (size_t)8 * O_;
#pragma unroll
            for (int j = 0; j < 8; ++j) {
                int col = j * 8 + (lane & 3) * 2;
                float2 v0, v1;
                v0.x = acc[t][j][0] + bi[j].x;
                v0.y = acc[t][j][1] + bi[j].y;
                v1.x = acc[t][j][2] + bi[j].x;
                v1.y = acc[t][j][3] + bi[j].y;
                *(float2*)(p0 + col) = v0;
                *(float2*)(p1 + col) = v1;
            }
        }
    }
}

extern "C" void kernel_launch(void* const* d_in, const int* in_sizes, int n_in,
                              void* d_out, int out_size) {
    const float* x         = (const float*)d_in[0];
    const int*   t_indices = (const int*)d_in[1];   // int32 (JAX x64 disabled)
    const float* time_emb  = (const float*)d_in[2];
    const float* base_w    = (const float*)d_in[3];
    const float* base_b    = (const float*)d_in[4];
    const float* spline_w  = (const float*)d_in[5];
    float* out = (float*)d_out;

    {
        int total = O_ * K_TOTAL;
        prep_W<<<(total + 255) / 256, 256>>>(base_w, spline_w);
    }
    // Materialize F once: M*96 8-wide groups, 512 thr/blk
    feat_kernel<<<(M_TOTAL * 96) / 512, 512>>>(x, t_indices, time_emb);

    cudaFuncSetAttribute(kan_hmma_kernel,
                         cudaFuncAttributeMaxDynamicSharedMemorySize, SMEM_BYTES);
    dim3 grid(O_ / BN, M_TOTAL / BM);   // (2, 384) = 768 CTAs
    kan_hmma_kernel<<<grid, THREADS, SMEM_BYTES>>>(base_b, out);
}

// round 12
// speedup vs baseline: 3.0208x; 1.1686x over previous
#include <cuda_runtime.h>
#include <cuda_fp16.h>
#include <cstdint>

// ---------------------------------------------------------------------------
// TimeAwareKAN via single GEMM  out[m,o] = sum_k F[m,k] * W[o,k] + b[o]
//   M = 49152, K = 768 (6 families x 128), O = 512
// R11: 2 CTAs/SM for cross-CTA overlap of barrier/scoreboard stalls.
//   BM=128, BN=128, 128 thr (4 warps, 64x64 tiles), 3-stage cp.async
//   (32KB/stage, 96KB/CTA -> 2 CTAs/SM). Issue kt+2 at loop top, tail
//   wait_group 1 (chunk kt+1 resident before its iteration).
//   F stays L2-resident across the 4 concurrent o-blocks.
// t_indices is int32 on device (JAX x64 disabled).
// ---------------------------------------------------------------------------

#define B_   4
#define H_   24
#define N_   512
#define C_   120
#define D_   128
#define O_   512
#define G_   5
#define M_TOTAL (B_ * H_ * N_)
#define K_TOTAL 768

#define BM 128
#define BN 128
#define KC 64                    // 64 fp16 = 128B rows -> SW128 native
#define NCHUNK (K_TOTAL / KC)    // 12
#define THREADS 128
#define NSTAGE 3

#define STAGE_BYTES 32768
#define SMEM_BYTES  (NSTAGE * STAGE_BYTES)   // 96KB -> 2 CTAs/SM

__device__ __half g_W_h[O_ * K_TOTAL];            // 0.75 MB
__device__ __half g_F[(size_t)M_TOTAL * K_TOTAL]; // 75.5 MB scratch

__global__ void prep_W(const float* __restrict__ base_w,
                       const float* __restrict__ spline_w) {
    int idx = blockIdx.x * blockDim.x + threadIdx.x;
    if (idx >= O_ * K_TOTAL) return;
    int n = idx / K_TOTAL, k = idx - n * K_TOTAL;
    int j = k >> 7, i = k & 127;
    float w = (j == 0) ? base_w[n * D_ + i]
                       : spline_w[(n * D_ + i) * G_ + (j - 1)];
    g_W_h[idx] = __float2half(w);
}

// ---- Feature kernel: one thread -> 8 contiguous k of one row ----
__global__ __launch_bounds__(512)
void feat_kernel(const float* __restrict__ x,
                 const int* __restrict__ t_indices,
                 const float* __restrict__ time_emb) {
    int g = blockIdx.x * 512 + threadIdx.x;        // < M*96
    int m = g / 96, c8 = g - m * 96;
    int j = c8 >> 4, i0 = (c8 & 15) * 8;

    float4 a, b;
    if (i0 < C_) {
        a = *(const float4*)(x + (size_t)m * C_ + i0);
        b = *(const float4*)(x + (size_t)m * C_ + i0 + 4);
    } else {                                       // i0 == 120: time emb
        int h = (m >> 9) % H_;
        int ts = t_indices[h];
        ts = min(max(ts, 0), H_ - 1);
        a = *(const float4*)(time_emb + ts * 8);
        b = *(const float4*)(time_emb + ts * 8 + 4);
    }
    float v[8] = {a.x, a.y, a.z, a.w, b.x, b.y, b.z, b.w};
    float f[8];
    if (j == 0) {
#pragma unroll
        for (int e = 0; e < 8; ++e)
            f[e] = __fdividef(v[e], 1.0f + __expf(-v[e]));
    } else {
        const float gc = -1.0f + 0.5f * (float)(j - 1);
#pragma unroll
        for (int e = 0; e < 8; ++e) {
            float t = (v[e] - gc) * 2.0f;
            f[e] = __expf(-t * t);
        }
    }
    __half2 h0 = __floats2half2_rn(f[0], f[1]);
    __half2 h1 = __floats2half2_rn(f[2], f[3]);
    __half2 h2 = __floats2half2_rn(f[4], f[5]);
    __half2 h3 = __floats2half2_rn(f[6], f[7]);
    uint4 o;
    o.x = *(uint32_t*)&h0; o.y = *(uint32_t*)&h1;
    o.z = *(uint32_t*)&h2; o.w = *(uint32_t*)&h3;
    *(uint4*)(g_F + (size_t)m * K_TOTAL + j * 128 + i0) = o;
}

// ---------------- helpers ----------------
__device__ __forceinline__ uint32_t s2u(const void* p) {
    uint32_t a;
    asm("{ .reg .u64 t; cvta.to.shared.u64 t, %1; cvt.u32.u64 %0, t; }"
        : "=r"(a) : "l"(p));
    return a;
}
#define SWZ(o) ((o) ^ (((o) >> 3) & 0x70))

__device__ __forceinline__ void ldsm4(uint32_t* r, uint32_t addr) {
    asm volatile("ldmatrix.sync.aligned.m8n8.x4.shared.b16 {%0,%1,%2,%3}, [%4];"
        : "=r"(r[0]), "=r"(r[1]), "=r"(r[2]), "=r"(r[3]) : "r"(addr));
}
__device__ __forceinline__ void mma16816(float* c, const uint32_t* a,
                                         const uint32_t* b) {
    asm volatile(
        "mma.sync.aligned.m16n8k16.row.col.f32.f16.f16.f32 "
        "{%0,%1,%2,%3}, {%4,%5,%6,%7}, {%8,%9}, {%0,%1,%2,%3};"
        : "+f"(c[0]), "+f"(c[1]), "+f"(c[2]), "+f"(c[3])
        : "r"(a[0]), "r"(a[1]), "r"(a[2]), "r"(a[3]), "r"(b[0]), "r"(b[1]));
}

__global__ __launch_bounds__(THREADS, 2)
void kan_hmma_kernel(const float* __restrict__ base_b,
                     float* __restrict__ out) {
    extern __shared__ char smem[];
    const uint32_t sb = s2u(smem);
    const int tid = threadIdx.x, wid = tid >> 5, lane = tid & 31;
    const int m0 = blockIdx.y * BM, o0 = blockIdx.x * BN;

    const int warp_m = wid & 1;        // 2 x 64-row tiles
    const int warp_n = wid >> 1;       // 2 x 64-col tiles

    // ---- per-lane ldmatrix address components (SW128) ----
    const uint32_t kaoff = ((lane >> 4) & 1) * 16;
    uint32_t aB[4], aX[4];
#pragma unroll
    for (int t = 0; t < 4; ++t) {
        int r = warp_m * 64 + t * 16 + ((lane >> 3) & 1) * 8 + (lane & 7);
        aB[t] = r * 128;
        aX[t] = (r & 7) * 16;
    }
    const uint32_t kboff = ((lane >> 3) & 1) * 16;
    uint32_t bB[4], bX[4];
#pragma unroll
    for (int ng = 0; ng < 4; ++ng) {
        int r = warp_n * 64 + ng * 16 + ((lane >> 4) & 1) * 8 + (lane & 7);
        bB[ng] = r * 128;
        bX[ng] = (r & 7) * 16;
    }

    float acc[4][8][4];                 // [m16 tile][n8 tile][frag] = 128 regs
#pragma unroll
    for (int t = 0; t < 4; ++t)
#pragma unroll
        for (int j = 0; j < 8; ++j)
#pragma unroll
            for (int e = 0; e < 4; ++e) acc[t][j][e] = 0.0f;

    auto issue_chunk = [&](int kt) {
        const int stage = kt % NSTAGE;
        const int k0 = kt * KC;
        const uint32_t fbase = sb + stage * STAGE_BYTES;
        const uint32_t wbase = fbase + 16384;
        // F: 128 rows x 8 units = 1024 -> 8/thread
#pragma unroll
        for (int s = 0; s < 8; ++s) {
            int v = tid + THREADS * s;
            int r = v >> 3, u = v & 7;
            const __half* src = g_F + (size_t)(m0 + r) * K_TOTAL + k0 + u * 8;
            uint32_t dst = fbase + SWZ((uint32_t)(r * 128 + u * 16));
            asm volatile("cp.async.cg.shared.global [%0], [%1], 16;"
                         :: "r"(dst), "l"(src));
        }
        // W: 128 rows x 8 units = 1024 -> 8/thread
#pragma unroll
        for (int s = 0; s < 8; ++s) {
            int v = tid + THREADS * s;
            int r = v >> 3, u = v & 7;
            const __half* src = g_W_h + (size_t)(o0 + r) * K_TOTAL + k0 + u * 8;
            uint32_t dst = wbase + SWZ((uint32_t)(r * 128 + u * 16));
            asm volatile("cp.async.cg.shared.global [%0], [%1], 16;"
                         :: "r"(dst), "l"(src));
        }
        asm volatile("cp.async.commit_group;" ::: "memory");
    };

    // ---- prologue: fill 2 stages ----
    issue_chunk(0);
    issue_chunk(1);
    asm volatile("cp.async.wait_group 1;" ::: "memory");   // chunk 0 resident
    __syncthreads();

    // ---- main loop: one commit group per iteration ----
#pragma unroll 1
    for (int kt = 0; kt < NCHUNK; ++kt) {
        // stage (kt+2)%3 != kt%3: safe to fill while reading stage kt%3
        if (kt + 2 < NCHUNK) {
            issue_chunk(kt + 2);
        } else {
            asm volatile("cp.async.commit_group;" ::: "memory");  // empty group
        }

        const uint32_t fb = sb + (kt % NSTAGE) * STAGE_BYTES;
        const uint32_t wb = fb + 16384;

#pragma unroll
        for (int s = 0; s < 4; ++s) {
            const uint32_t ka = s * 32 + kaoff;
            const uint32_t kb = s * 32 + kboff;
            uint32_t ah[4][4];
#pragma unroll
            for (int t = 0; t < 4; ++t)
                ldsm4(ah[t], fb + aB[t] + (ka ^ aX[t]));
#pragma unroll
            for (int ng = 0; ng < 4; ++ng) {
                uint32_t bh[4];
                ldsm4(bh, wb + bB[ng] + (kb ^ bX[ng]));
                // bh: {r0,r1} -> n8 tile ng*2, {r2,r3} -> tile ng*2+1
#pragma unroll
                for (int t = 0; t < 4; ++t) {
                    mma16816(acc[t][ng * 2 + 0], ah[t], bh + 0);
                    mma16816(acc[t][ng * 2 + 1], ah[t], bh + 2);
                }
            }
        }

        // pending groups: kt+1, kt+2 -> keep <=1 so chunk kt+1 is resident
        asm volatile("cp.async.wait_group 1;" ::: "memory");
        __syncthreads();
    }

    // ---- epilogue: + bias, float2 stores ----
    {
        const float* bb = base_b + o0 + warp_n * 64;
        float2 bi[8];
#pragma unroll
        for (int j = 0; j < 8; ++j)
            bi[j] = *(const float2*)(bb + j * 8 + (lane & 3) * 2);
#pragma unroll
        for (int t = 0; t < 4; ++t) {
            int r0 = m0 + warp_m * 64 + t * 16 + (lane >> 2);
            float* p0 = out + (size_t)r0 * O_ + o0 + warp_n * 64;
            float* p1 = p0 + (size_t)8 * O_;
#pragma unroll
            for (int j = 0; j < 8; ++j) {
                int col = j * 8 + (lane & 3) * 2;
                float2 v0, v1;
                v0.x = acc[t][j][0] + bi[j].x;
                v0.y = acc[t][j][1] + bi[j].y;
                v1.x = acc[t][j][2] + bi[j].x;
                v1.y = acc[t][j][3] + bi[j].y;
                *(float2*)(p0 + col) = v0;
                *(float2*)(p1 + col) = v1;
            }
        }
    }
}

extern "C" void kernel_launch(void* const* d_in, const int* in_sizes, int n_in,
                              void* d_out, int out_size) {
    const float* x         = (const float*)d_in[0];
    const int*   t_indices = (const int*)d_in[1];   // int32 (JAX x64 disabled)
    const float* time_emb  = (const float*)d_in[2];
    const float* base_w    = (const float*)d_in[3];
    const float* base_b    = (const float*)d_in[4];
    const float* spline_w  = (const float*)d_in[5];
    float* out = (float*)d_out;

    {
        int total = O_ * K_TOTAL;
        prep_W<<<(total + 255) / 256, 256>>>(base_w, spline_w);
    }
    // Materialize F once: M*96 8-wide groups, 512 thr/blk
    feat_kernel<<<(M_TOTAL * 96) / 512, 512>>>(x, t_indices, time_emb);

    cudaFuncSetAttribute(kan_hmma_kernel,
                         cudaFuncAttributeMaxDynamicSharedMemorySize, SMEM_BYTES);
    dim3 grid(O_ / BN, M_TOTAL / BM);   // (4, 384) = 1536 CTAs, 2/SM
    kan_hmma_kernel<<<grid, THREADS, SMEM_BYTES>>>(base_b, out);
}